// round 13
// baseline (speedup 1.0000x reference)
#include <cuda_runtime.h>
#include <cuda_fp16.h>
#include <cstdint>

// DGCNN: B=8, N=2048, k=32.  (sm_103 PTX target -> mma.sync f16 + ldmatrix)
// prep_misc -> knn -> proj1 -> edge1 -> prep_wf -> [proj,edge]x2 -> heads.
// R13: occupancy push. Edge kernels: 1 m16-tile/warp (acc 32 regs), PT=4,
// launch_bounds(256,3) => 24 warps/SM (was 16); cross-warp point-max via smem
// (bit-identical fmaxf order). Heads to (256,3). cp.async dropped (neutral).

#define NEG 0.2f
constexpr int B_  = 8;
constexpr int N_  = 2048;
constexpr int BN_ = B_ * N_;   // 16384
constexpr int K_  = 32;

// ---- scratch (device globals; no runtime allocation allowed) ----
__device__ float4 g_pos4[BN_];
__device__ int    g_idx[BN_ * K_];
__device__ float  g_p[BN_ * 128];
__device__ float  g_q[BN_ * 128];
__device__ float  g_x1[BN_ * 64];
__device__ float  g_x2[BN_ * 128];
__device__ float  g_x3[BN_ * 512];
__device__ __half g_h1[BN_ * 512];
__device__ float  g_h2[BN_ * 256];
__device__ __half g_wbT1[64 * 64];
__device__ __half g_wbT2[128 * 64];
__device__ __half g_wbT3[512 * 128];
__device__ __half g_wf1T[512 * 704];
__device__ __half g_wf2T[256 * 512];

__device__ __forceinline__ float lrelu(float v) { return v >= 0.f ? v : NEG * v; }

__device__ __forceinline__ uint32_t pack_f16x2(float lo, float hi) {
    uint32_t u;
    asm("cvt.rn.f16x2.f32 %0, %1, %2;" : "=r"(u) : "f"(hi), "f"(lo));
    return u;
}

__device__ __forceinline__ uint32_t smem_u32(const void* p) {
    uint32_t a;
    asm("{ .reg .u64 t; cvta.to.shared.u64 t, %1; cvt.u32.u64 %0, t; }" : "=r"(a) : "l"(p));
    return a;
}

__device__ __forceinline__ void mma16816(float d[4], const uint32_t a[4],
                                         const uint32_t b[2]) {
    asm volatile(
        "mma.sync.aligned.m16n8k16.row.col.f32.f16.f16.f32 "
        "{%0,%1,%2,%3}, {%4,%5,%6,%7}, {%8,%9}, {%0,%1,%2,%3};\n"
        : "+f"(d[0]), "+f"(d[1]), "+f"(d[2]), "+f"(d[3])
        : "r"(a[0]), "r"(a[1]), "r"(a[2]), "r"(a[3]), "r"(b[0]), "r"(b[1]));
}

#define LDSM4(r, addr) \
    asm volatile("ldmatrix.sync.aligned.m8n8.x4.shared.b16 {%0,%1,%2,%3}, [%4];" \
                 : "=r"((r)[0]), "=r"((r)[1]), "=r"((r)[2]), "=r"((r)[3]) \
                 : "r"(addr))

// ---------------- prep: pos4 (xyz + sq) + edge-weight transposes ----------------
__global__ void prep_misc(const float* __restrict__ pos,
                          const float* __restrict__ w1, const float* __restrict__ w2,
                          const float* __restrict__ w3, __half* __restrict__ t1,
                          __half* __restrict__ t2, __half* __restrict__ t3) {
    int t = blockIdx.x * 256 + threadIdx.x;
    if (t < BN_) {
        float x = pos[t * 3 + 0], y = pos[t * 3 + 1], z = pos[t * 3 + 2];
        g_pos4[t] = make_float4(x, y, z, fmaf(z, z, fmaf(y, y, x * x)));
    } else if (t < BN_ + 4096) {
        int e = t - BN_;
        int k = e >> 6, n = e & 63;
        t1[n * 64 + k] = __float2half_rn(w1[e]);
    } else if (t < BN_ + 12288) {
        int e = t - BN_ - 4096;
        int k = e >> 7, n = e & 127;
        t2[n * 64 + k] = __float2half_rn(w2[e]);
    } else if (t < BN_ + 77824) {
        int e = t - BN_ - 12288;
        int k = e >> 9, n = e & 511;
        t3[n * 128 + k] = __float2half_rn(w3[e]);
    }
}

// ---------------- head-weight transpose + f16 ----------------
__global__ void prep_wf(const float* __restrict__ wf1, const float* __restrict__ wf2,
                        __half* __restrict__ t1, __half* __restrict__ t2) {
    int t = blockIdx.x * 256 + threadIdx.x;
    if (t < 360448) {
        int n = t / 704, k = t - n * 704;
        t1[t] = __float2half_rn(wf1[k * 512 + n]);
    } else {
        int e = t - 360448;
        int n = e >> 9, k = e & 511;
        t2[e] = __float2half_rn(wf2[k * 256 + n]);
    }
}

// ---------------- kNN: REDUX + sorted-pop selection (pos4 distances) ----------
#define KCE(a, b) { \
    bool sw = (khi[a] > khi[b]) || (khi[a] == khi[b] && klo[a] > klo[b]); \
    unsigned th = sw ? khi[b] : khi[a], tl = sw ? klo[b] : klo[a]; \
    khi[b] = sw ? khi[a] : khi[b]; klo[b] = sw ? klo[a] : klo[b]; \
    khi[a] = th; klo[a] = tl; }
#define KSORT8() \
    KCE(0,1) KCE(2,3) KCE(4,5) KCE(6,7) \
    KCE(0,2) KCE(1,3) KCE(4,6) KCE(5,7) \
    KCE(1,2) KCE(5,6) \
    KCE(0,4) KCE(1,5) KCE(2,6) KCE(3,7) \
    KCE(2,4) KCE(3,5) \
    KCE(1,2) KCE(3,4) KCE(5,6)

__global__ __launch_bounds__(256) void knn_kernel() {
    __shared__ unsigned long long cand[256];
    int point = blockIdx.x;
    int base  = (point >> 11) * N_;
    int tid   = threadIdx.x;
    int w     = tid >> 5, lane = tid & 31;

    float4 pq = g_pos4[point];
    float sqn = pq.w;

    {
        unsigned khi[8], klo[8];
#pragma unroll
        for (int i = 0; i < 8; i++) {
            int m = (w << 8) + (i << 5) + lane;
            float4 pm = g_pos4[base + m];
            float dot = fmaf(pq.z, pm.z, fmaf(pq.y, pm.y, pq.x * pm.x));
            float d2  = (sqn - 2.f * dot) + pm.w;
            unsigned u = __float_as_uint(d2);
            khi[i] = (u & 0x80000000u) ? ~u : (u | 0x80000000u);
            klo[i] = (unsigned)m;
        }
        KSORT8();

#pragma unroll 4
        for (int it = 0; it < K_; it++) {
            unsigned mhi  = __reduce_min_sync(0xffffffffu, khi[0]);
            unsigned prop = (khi[0] == mhi) ? klo[0] : 0xFFFFFFFFu;
            unsigned mlo  = __reduce_min_sync(0xffffffffu, prop);
            if (lane == 0)
                cand[(w << 5) + it] = ((unsigned long long)mhi << 32) | mlo;
            if (prop == mlo) {
#pragma unroll
                for (int i = 0; i < 7; i++) { khi[i] = khi[i + 1]; klo[i] = klo[i + 1]; }
                khi[7] = 0xFFFFFFFFu; klo[7] = 0xFFFFFFFFu;
            }
        }
    }
    __syncthreads();

    if (w == 0) {
        unsigned khi[8], klo[8];
#pragma unroll
        for (int i = 0; i < 8; i++) {
            unsigned long long c = cand[(i << 5) + lane];
            khi[i] = (unsigned)(c >> 32);
            klo[i] = (unsigned)c;
        }
        KSORT8();

#pragma unroll 4
        for (int it = 0; it < K_; it++) {
            unsigned mhi  = __reduce_min_sync(0xffffffffu, khi[0]);
            unsigned prop = (khi[0] == mhi) ? klo[0] : 0xFFFFFFFFu;
            unsigned mlo  = __reduce_min_sync(0xffffffffu, prop);
            if (lane == 0) g_idx[point * K_ + it] = base + (int)mlo;
            if (prop == mlo) {
#pragma unroll
                for (int i = 0; i < 7; i++) { khi[i] = khi[i + 1]; klo[i] = klo[i + 1]; }
                khi[7] = 0xFFFFFFFFu; klo[7] = 0xFFFFFFFFu;
            }
        }
    }
}

// ---------------- batched per-point projections p,q ----------------
template <int CIN, int CMID, int CINP>
__global__ __launch_bounds__(256) void proj_kernel(const float* __restrict__ x,
                                                   const float* __restrict__ wa,
                                                   const float* __restrict__ ba) {
    extern __shared__ __align__(16) float smf[];
    float* wts = smf;
    float* wqs = wts + CMID * CINP;
    float* xs  = wqs + CMID * CINP;
    float* bas = xs + 32 * CINP;
    int tid = threadIdx.x;
    int p0  = blockIdx.x * 32;

    for (int t = tid; t < CIN * CMID; t += 256) {
        int ci = t / CMID, cm = t - ci * CMID;
        float top = wa[t], bot = wa[CIN * CMID + t];
        wts[cm * CINP + ci] = top - bot;
        wqs[cm * CINP + ci] = bot;
    }
    for (int t = tid; t < 32 * CIN; t += 256) {
        int pp = t / CIN, ci = t - pp * CIN;
        xs[pp * CINP + ci] = x[(size_t)(p0 + pp) * CIN + ci];
    }
    if (tid < CMID) bas[tid] = ba[tid];
    __syncthreads();

    constexpr int LANES = 256 / CMID;
    int li = tid / CMID, cm = tid - li * CMID;
    const float* wtr = wts + cm * CINP;
    const float* wqr = wqs + cm * CINP;
    float bias = bas[cm];

    for (int pp = li; pp < 32; pp += LANES) {
        const float* xr = xs + pp * CINP;
        float pa = bias, qa = 0.f;
        if constexpr (CIN % 4 == 0) {
#pragma unroll
            for (int ci = 0; ci < CIN; ci += 4) {
                float4 xv = *(const float4*)(xr + ci);
                float4 wt4 = *(const float4*)(wtr + ci);
                float4 wq4 = *(const float4*)(wqr + ci);
                pa = fmaf(xv.x, wt4.x, pa); qa = fmaf(xv.x, wq4.x, qa);
                pa = fmaf(xv.y, wt4.y, pa); qa = fmaf(xv.y, wq4.y, qa);
                pa = fmaf(xv.z, wt4.z, pa); qa = fmaf(xv.z, wq4.z, qa);
                pa = fmaf(xv.w, wt4.w, pa); qa = fmaf(xv.w, wq4.w, qa);
            }
        } else {
#pragma unroll
            for (int ci = 0; ci < CIN; ci++) {
                float xv = xr[ci];
                pa = fmaf(xv, wtr[ci], pa);
                qa = fmaf(xv, wqr[ci], qa);
            }
        }
        g_p[(size_t)(p0 + pp) * CMID + cm] = pa;
        g_q[(size_t)(p0 + pp) * CMID + cm] = qa;
    }
}

// ---------------- edge blocks: f16 mma + ldmatrix, 1 m-tile/warp, 3 blk/SM ----
// Block: 4 points (A = 128 edge rows gathered ONCE), 8 warps = 8 m16 tiles.
// Warp w covers rows [w*16, w*16+16) = half of point w>>1. NITER n-slices of 64.
// Epilogue: 16-row colmax in regs+shfl, cross-warp-pair max via smem (fmaxf
// is exactly associative -> bit-identical to the 32-row sequence).
template <int CMID, int COUT, int NITER>
__global__ __launch_bounds__(256, 3) void edge_mma(const __half* __restrict__ wbT,
                                                   const float* __restrict__ bb,
                                                   float* __restrict__ out) {
    constexpr int PT    = 4;
    constexpr int NT    = 64;
    constexpr int KP    = CMID + 8;
    constexpr int AROWS = PT * 32;         // 128
    constexpr int CPR8  = CMID / 8;
    extern __shared__ __align__(16) char smraw[];
    __half* As  = (__half*)smraw;               // [128][KP]
    __half* Bs  = As + AROWS * KP;              // [64][KP]
    int*   nidx = (int*)(Bs + NT * KP);         // [128]
    float* red  = (float*)(nidx + AROWS);       // [8][64]

    int tid = threadIdx.x, w = tid >> 5, lane = tid & 31;
    int p0 = blockIdx.x * PT;

    if (tid < AROWS) nidx[tid] = g_idx[p0 * K_ + tid];
    __syncthreads();

    // A fill (once): row r=(pt,nbr): lrelu(p + q[nb]) -> f16
#pragma unroll
    for (int i = 0; i < AROWS * CPR8 / 256; i++) {
        int e  = i * 256 + tid;
        int r  = e / CPR8;
        int c0 = (e - r * CPR8) * 8;
        const float* qr = g_q + (size_t)nidx[r] * CMID + c0;
        const float* pr = g_p + (size_t)(p0 + (r >> 5)) * CMID + c0;
        float4 qa = *(const float4*)qr, qb = *(const float4*)(qr + 4);
        float4 pa = *(const float4*)pr, pb = *(const float4*)(pr + 4);
        uint4 pk = { pack_f16x2(lrelu(pa.x + qa.x), lrelu(pa.y + qa.y)),
                     pack_f16x2(lrelu(pa.z + qa.z), lrelu(pa.w + qa.w)),
                     pack_f16x2(lrelu(pb.x + qb.x), lrelu(pb.y + qb.y)),
                     pack_f16x2(lrelu(pb.z + qb.z), lrelu(pb.w + qb.w)) };
        *(uint4*)(As + r * KP + c0) = pk;
    }

    uint32_t aBase = smem_u32(As) +
        (uint32_t)(((w * 16 + (lane & 15)) * KP + (lane >> 4) * 8) * 2);
    uint32_t bBase = smem_u32(Bs) +
        (uint32_t)((((lane & 7) + ((lane >> 4) << 3)) * KP + ((lane >> 3) & 1) * 8) * 2);

#pragma unroll 1
    for (int it = 0; it < NITER; it++) {
        int n0 = it * NT;
        __syncthreads();   // A ready (it==0) / prior epilogue reads done
        // B fill
#pragma unroll
        for (int i = 0; i < NT * CPR8 / 256; i++) {
            int e  = i * 256 + tid;
            int r  = e / CPR8;
            int c0 = (e - r * CPR8) * 8;
            *(uint4*)(Bs + r * KP + c0) =
                *(const uint4*)(wbT + (size_t)(n0 + r) * CMID + c0);
        }
        __syncthreads();

        float acc[8][4];
#pragma unroll
        for (int nt = 0; nt < 8; nt++)
#pragma unroll
            for (int j = 0; j < 4; j++) acc[nt][j] = 0.f;

#pragma unroll 1
        for (int ks = 0; ks < CMID / 16; ks++) {
            uint32_t a[4];
            LDSM4(a, aBase + ks * 32);
#pragma unroll
            for (int ntp = 0; ntp < 4; ntp++) {
                uint32_t b[4];
                LDSM4(b, bBase + ntp * (16 * KP * 2) + ks * 32);
                mma16816(acc[2 * ntp],     a, b + 0);
                mma16816(acc[2 * ntp + 1], a, b + 2);
            }
        }

        // epilogue: 16-row colmax per warp -> smem; pairwise max across the
        // two warps of each point; lrelu(max + bias).
#pragma unroll
        for (int nt = 0; nt < 8; nt++) {
            float v0 = fmaxf(acc[nt][0], acc[nt][2]);
            float v1 = fmaxf(acc[nt][1], acc[nt][3]);
#pragma unroll
            for (int s = 4; s < 32; s <<= 1) {
                v0 = fmaxf(v0, __shfl_xor_sync(0xffffffffu, v0, s));
                v1 = fmaxf(v1, __shfl_xor_sync(0xffffffffu, v1, s));
            }
            if (lane < 4) {
                red[w * 64 + nt * 8 + 2 * lane]     = v0;
                red[w * 64 + nt * 8 + 2 * lane + 1] = v1;
            }
        }
        __syncthreads();
        {
            int pp = tid >> 6, c = tid & 63;
            float m = fmaxf(red[(2 * pp) * 64 + c], red[(2 * pp + 1) * 64 + c]);
            int col = n0 + c;
            out[(size_t)(p0 + pp) * COUT + col] = lrelu(m + bb[col]);
        }
    }
}

// ---------------- head1: concat(704) -> 512 via f16 mma, lrelu, h1 f16 --------
__global__ __launch_bounds__(256, 3) void head1_mma(const __half* __restrict__ wT,
                                                    const float* __restrict__ bias) {
    __shared__ __align__(16) __half As[64 * 72];
    __shared__ __align__(16) __half Bs[128 * 72];
    int tid = threadIdx.x, w = tid >> 5, lane = tid & 31;
    int m0 = blockIdx.x * 64, n0 = blockIdx.y * 128;
    int mt = (w >> 1) * 16, ng = (w & 1) * 64;

    float acc[8][4];
#pragma unroll
    for (int nt = 0; nt < 8; nt++)
#pragma unroll
        for (int j = 0; j < 4; j++) acc[nt][j] = 0.f;

    uint32_t aBase = smem_u32(As) +
        (uint32_t)(((mt + (lane & 15)) * 72 + (lane >> 4) * 8) * 2);
    uint32_t bBase = smem_u32(Bs) +
        (uint32_t)(((ng + (lane & 7) + ((lane >> 4) << 3)) * 72 + ((lane >> 3) & 1) * 8) * 2);

#pragma unroll 1
    for (int kc = 0; kc < 11; kc++) {
        const float* src; int stride, off;
        if (kc == 0)      { src = g_x1; stride = 64;  off = 0; }
        else if (kc <= 2) { src = g_x2; stride = 128; off = (kc - 1) * 64; }
        else              { src = g_x3; stride = 512; off = (kc - 3) * 64; }
#pragma unroll
        for (int i = 0; i < 2; i++) {
            int t = i * 256 + tid;
            int r = t >> 3, c0 = (t & 7) * 8;
            const float* sp = src + (size_t)(m0 + r) * stride + off + c0;
            float4 a = *(const float4*)sp, b = *(const float4*)(sp + 4);
            uint4 pk = { pack_f16x2(a.x, a.y), pack_f16x2(a.z, a.w),
                         pack_f16x2(b.x, b.y), pack_f16x2(b.z, b.w) };
            *(uint4*)(As + r * 72 + c0) = pk;
        }
#pragma unroll
        for (int i = 0; i < 4; i++) {
            int t = i * 256 + tid;
            int r = t >> 3, c0 = (t & 7) * 8;
            *(uint4*)(Bs + r * 72 + c0) =
                *(const uint4*)(wT + (size_t)(n0 + r) * 704 + kc * 64 + c0);
        }
        __syncthreads();
#pragma unroll
        for (int ks = 0; ks < 4; ks++) {
            uint32_t a[4];
            LDSM4(a, aBase + ks * 32);
#pragma unroll
            for (int ntp = 0; ntp < 4; ntp++) {
                uint32_t b[4];
                LDSM4(b, bBase + ntp * (16 * 72 * 2) + ks * 32);
                mma16816(acc[2 * ntp],     a, b + 0);
                mma16816(acc[2 * ntp + 1], a, b + 2);
            }
        }
        __syncthreads();
    }

    int gid = lane >> 2, tig = lane & 3;
    int row = m0 + mt + gid;
#pragma unroll
    for (int nt = 0; nt < 8; nt++) {
        int col = n0 + ng + nt * 8 + 2 * tig;
        float b0 = bias[col], b1 = bias[col + 1];
        *(uint32_t*)(g_h1 + (size_t)row * 512 + col) =
            pack_f16x2(lrelu(acc[nt][0] + b0), lrelu(acc[nt][1] + b1));
        *(uint32_t*)(g_h1 + (size_t)(row + 8) * 512 + col) =
            pack_f16x2(lrelu(acc[nt][2] + b0), lrelu(acc[nt][3] + b1));
    }
}

// ---------------- head2: 512 -> 256 via f16 mma, lrelu, h2 fp32 ---------------
__global__ __launch_bounds__(256, 3) void head2_mma(const __half* __restrict__ wT,
                                                    const float* __restrict__ bias) {
    __shared__ __align__(16) __half As[64 * 72];
    __shared__ __align__(16) __half Bs[128 * 72];
    int tid = threadIdx.x, w = tid >> 5, lane = tid & 31;
    int m0 = blockIdx.x * 64, n0 = blockIdx.y * 128;
    int mt = (w >> 1) * 16, ng = (w & 1) * 64;

    float acc[8][4];
#pragma unroll
    for (int nt = 0; nt < 8; nt++)
#pragma unroll
        for (int j = 0; j < 4; j++) acc[nt][j] = 0.f;

    uint32_t aBase = smem_u32(As) +
        (uint32_t)(((mt + (lane & 15)) * 72 + (lane >> 4) * 8) * 2);
    uint32_t bBase = smem_u32(Bs) +
        (uint32_t)(((ng + (lane & 7) + ((lane >> 4) << 3)) * 72 + ((lane >> 3) & 1) * 8) * 2);

#pragma unroll 1
    for (int kc = 0; kc < 8; kc++) {
#pragma unroll
        for (int i = 0; i < 2; i++) {
            int t = i * 256 + tid;
            int r = t >> 3, c0 = (t & 7) * 8;
            *(uint4*)(As + r * 72 + c0) =
                *(const uint4*)(g_h1 + (size_t)(m0 + r) * 512 + kc * 64 + c0);
        }
#pragma unroll
        for (int i = 0; i < 4; i++) {
            int t = i * 256 + tid;
            int r = t >> 3, c0 = (t & 7) * 8;
            *(uint4*)(Bs + r * 72 + c0) =
                *(const uint4*)(wT + (size_t)(n0 + r) * 512 + kc * 64 + c0);
        }
        __syncthreads();
#pragma unroll
        for (int ks = 0; ks < 4; ks++) {
            uint32_t a[4];
            LDSM4(a, aBase + ks * 32);
#pragma unroll
            for (int ntp = 0; ntp < 4; ntp++) {
                uint32_t b[4];
                LDSM4(b, bBase + ntp * (16 * 72 * 2) + ks * 32);
                mma16816(acc[2 * ntp],     a, b + 0);
                mma16816(acc[2 * ntp + 1], a, b + 2);
            }
        }
        __syncthreads();
    }

    int gid = lane >> 2, tig = lane & 3;
    int row = m0 + mt + gid;
#pragma unroll
    for (int nt = 0; nt < 8; nt++) {
        int col = n0 + ng + nt * 8 + 2 * tig;
        float b0 = bias[col], b1 = bias[col + 1];
        g_h2[(size_t)row * 256 + col]           = lrelu(acc[nt][0] + b0);
        g_h2[(size_t)row * 256 + col + 1]       = lrelu(acc[nt][1] + b1);
        g_h2[(size_t)(row + 8) * 256 + col]     = lrelu(acc[nt][2] + b0);
        g_h2[(size_t)(row + 8) * 256 + col + 1] = lrelu(acc[nt][3] + b1);
    }
}

// ---------------- head3: 256 -> 12 (fp32, no lrelu) ----------------
__global__ __launch_bounds__(192) void head3_kernel(const float* __restrict__ wf3,
                                                    const float* __restrict__ bf3,
                                                    float* __restrict__ out) {
    int blk = blockIdx.x, tid = threadIdx.x;
    int r = tid / 12, c = tid - r * 12;
    int row = blk * 16 + r;
    const float* h = g_h2 + (size_t)row * 256;
    float a0 = bf3[c], a1 = 0.f, a2 = 0.f, a3 = 0.f;
#pragma unroll 4
    for (int cm = 0; cm < 256; cm += 4) {
        a0 = fmaf(h[cm + 0], wf3[(cm + 0) * 12 + c], a0);
        a1 = fmaf(h[cm + 1], wf3[(cm + 1) * 12 + c], a1);
        a2 = fmaf(h[cm + 2], wf3[(cm + 2) * 12 + c], a2);
        a3 = fmaf(h[cm + 3], wf3[(cm + 3) * 12 + c], a3);
    }
    out[(size_t)row * 12 + c] = (a0 + a1) + (a2 + a3);
}

// ---------------- launch ----------------
constexpr int SMEM_P1 = (2 * 64 * 4 + 32 * 4 + 64) * 4;
constexpr int SMEM_P2 = (2 * 64 * 68 + 32 * 68 + 64) * 4;
constexpr int SMEM_P3 = (2 * 128 * 132 + 32 * 132 + 128) * 4;
constexpr int SMEM_E12 = (128 * 72 + 64 * 72) * 2 + 128 * 4 + 8 * 64 * 4;  // 30208
constexpr int SMEM_E3  = (128 * 136 + 64 * 136) * 2 + 128 * 4 + 8 * 64 * 4; // 54784

extern "C" void kernel_launch(void* const* d_in, const int* in_sizes, int n_in,
                              void* d_out, int out_size) {
    const float* x   = (const float*)d_in[0];
    const float* pos = (const float*)d_in[1];
    const float* w1a = (const float*)d_in[2];
    const float* b1a = (const float*)d_in[3];
    const float* w1b = (const float*)d_in[4];
    const float* b1b = (const float*)d_in[5];
    const float* w2a = (const float*)d_in[6];
    const float* b2a = (const float*)d_in[7];
    const float* w2b = (const float*)d_in[8];
    const float* b2b = (const float*)d_in[9];
    const float* w3a = (const float*)d_in[10];
    const float* b3a = (const float*)d_in[11];
    const float* w3b = (const float*)d_in[12];
    const float* b3b = (const float*)d_in[13];
    const float* wf1 = (const float*)d_in[14];
    const float* bf1 = (const float*)d_in[15];
    const float* wf2 = (const float*)d_in[16];
    const float* bf2 = (const float*)d_in[17];
    const float* wf3 = (const float*)d_in[18];
    const float* bf3 = (const float*)d_in[19];
    float* out = (float*)d_out;

    float *x1p, *x2p, *x3p;
    __half *wt1p, *wt2p, *wt3p, *wf1Tp, *wf2Tp;
    cudaGetSymbolAddress((void**)&x1p, g_x1);
    cudaGetSymbolAddress((void**)&x2p, g_x2);
    cudaGetSymbolAddress((void**)&x3p, g_x3);
    cudaGetSymbolAddress((void**)&wt1p, g_wbT1);
    cudaGetSymbolAddress((void**)&wt2p, g_wbT2);
    cudaGetSymbolAddress((void**)&wt3p, g_wbT3);
    cudaGetSymbolAddress((void**)&wf1Tp, g_wf1T);
    cudaGetSymbolAddress((void**)&wf2Tp, g_wf2T);

    static bool attr_done = false;
    if (!attr_done) {
        cudaFuncSetAttribute(proj_kernel<128, 128, 132>,
                             cudaFuncAttributeMaxDynamicSharedMemorySize, SMEM_P3);
        cudaFuncSetAttribute(edge_mma<64, 64, 1>,
                             cudaFuncAttributeMaxDynamicSharedMemorySize, SMEM_E12);
        cudaFuncSetAttribute(edge_mma<64, 128, 2>,
                             cudaFuncAttributeMaxDynamicSharedMemorySize, SMEM_E12);
        cudaFuncSetAttribute(edge_mma<128, 512, 8>,
                             cudaFuncAttributeMaxDynamicSharedMemorySize, SMEM_E3);
        attr_done = true;
    }

    // slot 4 (the launch ncu captures) = edge1, to verify the occupancy theory
    prep_misc<<<368, 256>>>(pos, w1b, w2b, w3b, wt1p, wt2p, wt3p);         // 1
    knn_kernel<<<BN_, 256>>>();                                            // 2
    proj_kernel<3, 64, 4><<<BN_ / 32, 256, SMEM_P1>>>(x, w1a, b1a);        // 3
    edge_mma<64, 64, 1><<<BN_ / 4, 256, SMEM_E12>>>(wt1p, b1b, x1p);       // 4 <- ncu
    prep_wf<<<1920, 256>>>(wf1, wf2, wf1Tp, wf2Tp);                        // 5

    // block2: 64 -> 64 -> 128
    proj_kernel<64, 64, 68><<<BN_ / 32, 256, SMEM_P2>>>(x1p, w2a, b2a);
    edge_mma<64, 128, 2><<<BN_ / 4, 256, SMEM_E12>>>(wt2p, b2b, x2p);
    // block3: 128 -> 128 -> 512
    proj_kernel<128, 128, 132><<<BN_ / 32, 256, SMEM_P3>>>(x2p, w3a, b3a);
    edge_mma<128, 512, 8><<<BN_ / 4, 256, SMEM_E3>>>(wt3p, b3b, x3p);

    // head: 704 -> 512 (f16 mma) -> 256 (f16 mma) -> 12 (fp32)
    head1_mma<<<dim3(BN_ / 64, 4), 256>>>(wf1Tp, bf1);
    head2_mma<<<dim3(BN_ / 64, 2), 256>>>(wf2Tp, bf2);
    head3_kernel<<<BN_ / 16, 192>>>(wf3, bf3, out);
}

// round 14
// speedup vs baseline: 1.1012x; 1.1012x over previous
#include <cuda_runtime.h>
#include <cuda_fp16.h>
#include <cstdint>

// DGCNN: B=8, N=2048, k=32.  (sm_103 PTX target -> mma.sync f16 + ldmatrix)
// prep_misc -> knn -> proj1 -> edge1 -> prep_wf -> [proj,edge]x2 -> heads.
// R14: split edge configs. edge1/2: PT=4, (256,3) [R13's measured win for
// small NITER]. edge3: PT=8, (256,2) [R11's best; half the B traffic].
// Heads back to (256,2). pos4 knn kept; cp.async dropped.

#define NEG 0.2f
constexpr int B_  = 8;
constexpr int N_  = 2048;
constexpr int BN_ = B_ * N_;   // 16384
constexpr int K_  = 32;

// ---- scratch (device globals; no runtime allocation allowed) ----
__device__ float4 g_pos4[BN_];
__device__ int    g_idx[BN_ * K_];
__device__ float  g_p[BN_ * 128];
__device__ float  g_q[BN_ * 128];
__device__ float  g_x1[BN_ * 64];
__device__ float  g_x2[BN_ * 128];
__device__ float  g_x3[BN_ * 512];
__device__ __half g_h1[BN_ * 512];
__device__ float  g_h2[BN_ * 256];
__device__ __half g_wbT1[64 * 64];
__device__ __half g_wbT2[128 * 64];
__device__ __half g_wbT3[512 * 128];
__device__ __half g_wf1T[512 * 704];
__device__ __half g_wf2T[256 * 512];

__device__ __forceinline__ float lrelu(float v) { return v >= 0.f ? v : NEG * v; }

__device__ __forceinline__ uint32_t pack_f16x2(float lo, float hi) {
    uint32_t u;
    asm("cvt.rn.f16x2.f32 %0, %1, %2;" : "=r"(u) : "f"(hi), "f"(lo));
    return u;
}

__device__ __forceinline__ uint32_t smem_u32(const void* p) {
    uint32_t a;
    asm("{ .reg .u64 t; cvta.to.shared.u64 t, %1; cvt.u32.u64 %0, t; }" : "=r"(a) : "l"(p));
    return a;
}

__device__ __forceinline__ void mma16816(float d[4], const uint32_t a[4],
                                         const uint32_t b[2]) {
    asm volatile(
        "mma.sync.aligned.m16n8k16.row.col.f32.f16.f16.f32 "
        "{%0,%1,%2,%3}, {%4,%5,%6,%7}, {%8,%9}, {%0,%1,%2,%3};\n"
        : "+f"(d[0]), "+f"(d[1]), "+f"(d[2]), "+f"(d[3])
        : "r"(a[0]), "r"(a[1]), "r"(a[2]), "r"(a[3]), "r"(b[0]), "r"(b[1]));
}

#define LDSM4(r, addr) \
    asm volatile("ldmatrix.sync.aligned.m8n8.x4.shared.b16 {%0,%1,%2,%3}, [%4];" \
                 : "=r"((r)[0]), "=r"((r)[1]), "=r"((r)[2]), "=r"((r)[3]) \
                 : "r"(addr))

// ---------------- prep: pos4 (xyz + sq) + edge-weight transposes ----------------
__global__ void prep_misc(const float* __restrict__ pos,
                          const float* __restrict__ w1, const float* __restrict__ w2,
                          const float* __restrict__ w3, __half* __restrict__ t1,
                          __half* __restrict__ t2, __half* __restrict__ t3) {
    int t = blockIdx.x * 256 + threadIdx.x;
    if (t < BN_) {
        float x = pos[t * 3 + 0], y = pos[t * 3 + 1], z = pos[t * 3 + 2];
        g_pos4[t] = make_float4(x, y, z, fmaf(z, z, fmaf(y, y, x * x)));
    } else if (t < BN_ + 4096) {
        int e = t - BN_;
        int k = e >> 6, n = e & 63;
        t1[n * 64 + k] = __float2half_rn(w1[e]);
    } else if (t < BN_ + 12288) {
        int e = t - BN_ - 4096;
        int k = e >> 7, n = e & 127;
        t2[n * 64 + k] = __float2half_rn(w2[e]);
    } else if (t < BN_ + 77824) {
        int e = t - BN_ - 12288;
        int k = e >> 9, n = e & 511;
        t3[n * 128 + k] = __float2half_rn(w3[e]);
    }
}

// ---------------- head-weight transpose + f16 ----------------
__global__ void prep_wf(const float* __restrict__ wf1, const float* __restrict__ wf2,
                        __half* __restrict__ t1, __half* __restrict__ t2) {
    int t = blockIdx.x * 256 + threadIdx.x;
    if (t < 360448) {
        int n = t / 704, k = t - n * 704;
        t1[t] = __float2half_rn(wf1[k * 512 + n]);
    } else {
        int e = t - 360448;
        int n = e >> 9, k = e & 511;
        t2[e] = __float2half_rn(wf2[k * 256 + n]);
    }
}

// ---------------- kNN: REDUX + sorted-pop selection (pos4 distances) ----------
#define KCE(a, b) { \
    bool sw = (khi[a] > khi[b]) || (khi[a] == khi[b] && klo[a] > klo[b]); \
    unsigned th = sw ? khi[b] : khi[a], tl = sw ? klo[b] : klo[a]; \
    khi[b] = sw ? khi[a] : khi[b]; klo[b] = sw ? klo[a] : klo[b]; \
    khi[a] = th; klo[a] = tl; }
#define KSORT8() \
    KCE(0,1) KCE(2,3) KCE(4,5) KCE(6,7) \
    KCE(0,2) KCE(1,3) KCE(4,6) KCE(5,7) \
    KCE(1,2) KCE(5,6) \
    KCE(0,4) KCE(1,5) KCE(2,6) KCE(3,7) \
    KCE(2,4) KCE(3,5) \
    KCE(1,2) KCE(3,4) KCE(5,6)

__global__ __launch_bounds__(256) void knn_kernel() {
    __shared__ unsigned long long cand[256];
    int point = blockIdx.x;
    int base  = (point >> 11) * N_;
    int tid   = threadIdx.x;
    int w     = tid >> 5, lane = tid & 31;

    float4 pq = g_pos4[point];
    float sqn = pq.w;

    {
        unsigned khi[8], klo[8];
#pragma unroll
        for (int i = 0; i < 8; i++) {
            int m = (w << 8) + (i << 5) + lane;
            float4 pm = g_pos4[base + m];
            float dot = fmaf(pq.z, pm.z, fmaf(pq.y, pm.y, pq.x * pm.x));
            float d2  = (sqn - 2.f * dot) + pm.w;
            unsigned u = __float_as_uint(d2);
            khi[i] = (u & 0x80000000u) ? ~u : (u | 0x80000000u);
            klo[i] = (unsigned)m;
        }
        KSORT8();

#pragma unroll 4
        for (int it = 0; it < K_; it++) {
            unsigned mhi  = __reduce_min_sync(0xffffffffu, khi[0]);
            unsigned prop = (khi[0] == mhi) ? klo[0] : 0xFFFFFFFFu;
            unsigned mlo  = __reduce_min_sync(0xffffffffu, prop);
            if (lane == 0)
                cand[(w << 5) + it] = ((unsigned long long)mhi << 32) | mlo;
            if (prop == mlo) {
#pragma unroll
                for (int i = 0; i < 7; i++) { khi[i] = khi[i + 1]; klo[i] = klo[i + 1]; }
                khi[7] = 0xFFFFFFFFu; klo[7] = 0xFFFFFFFFu;
            }
        }
    }
    __syncthreads();

    if (w == 0) {
        unsigned khi[8], klo[8];
#pragma unroll
        for (int i = 0; i < 8; i++) {
            unsigned long long c = cand[(i << 5) + lane];
            khi[i] = (unsigned)(c >> 32);
            klo[i] = (unsigned)c;
        }
        KSORT8();

#pragma unroll 4
        for (int it = 0; it < K_; it++) {
            unsigned mhi  = __reduce_min_sync(0xffffffffu, khi[0]);
            unsigned prop = (khi[0] == mhi) ? klo[0] : 0xFFFFFFFFu;
            unsigned mlo  = __reduce_min_sync(0xffffffffu, prop);
            if (lane == 0) g_idx[point * K_ + it] = base + (int)mlo;
            if (prop == mlo) {
#pragma unroll
                for (int i = 0; i < 7; i++) { khi[i] = khi[i + 1]; klo[i] = klo[i + 1]; }
                khi[7] = 0xFFFFFFFFu; klo[7] = 0xFFFFFFFFu;
            }
        }
    }
}

// ---------------- batched per-point projections p,q ----------------
template <int CIN, int CMID, int CINP>
__global__ __launch_bounds__(256) void proj_kernel(const float* __restrict__ x,
                                                   const float* __restrict__ wa,
                                                   const float* __restrict__ ba) {
    extern __shared__ __align__(16) float smf[];
    float* wts = smf;
    float* wqs = wts + CMID * CINP;
    float* xs  = wqs + CMID * CINP;
    float* bas = xs + 32 * CINP;
    int tid = threadIdx.x;
    int p0  = blockIdx.x * 32;

    for (int t = tid; t < CIN * CMID; t += 256) {
        int ci = t / CMID, cm = t - ci * CMID;
        float top = wa[t], bot = wa[CIN * CMID + t];
        wts[cm * CINP + ci] = top - bot;
        wqs[cm * CINP + ci] = bot;
    }
    for (int t = tid; t < 32 * CIN; t += 256) {
        int pp = t / CIN, ci = t - pp * CIN;
        xs[pp * CINP + ci] = x[(size_t)(p0 + pp) * CIN + ci];
    }
    if (tid < CMID) bas[tid] = ba[tid];
    __syncthreads();

    constexpr int LANES = 256 / CMID;
    int li = tid / CMID, cm = tid - li * CMID;
    const float* wtr = wts + cm * CINP;
    const float* wqr = wqs + cm * CINP;
    float bias = bas[cm];

    for (int pp = li; pp < 32; pp += LANES) {
        const float* xr = xs + pp * CINP;
        float pa = bias, qa = 0.f;
        if constexpr (CIN % 4 == 0) {
#pragma unroll
            for (int ci = 0; ci < CIN; ci += 4) {
                float4 xv = *(const float4*)(xr + ci);
                float4 wt4 = *(const float4*)(wtr + ci);
                float4 wq4 = *(const float4*)(wqr + ci);
                pa = fmaf(xv.x, wt4.x, pa); qa = fmaf(xv.x, wq4.x, qa);
                pa = fmaf(xv.y, wt4.y, pa); qa = fmaf(xv.y, wq4.y, qa);
                pa = fmaf(xv.z, wt4.z, pa); qa = fmaf(xv.z, wq4.z, qa);
                pa = fmaf(xv.w, wt4.w, pa); qa = fmaf(xv.w, wq4.w, qa);
            }
        } else {
#pragma unroll
            for (int ci = 0; ci < CIN; ci++) {
                float xv = xr[ci];
                pa = fmaf(xv, wtr[ci], pa);
                qa = fmaf(xv, wqr[ci], qa);
            }
        }
        g_p[(size_t)(p0 + pp) * CMID + cm] = pa;
        g_q[(size_t)(p0 + pp) * CMID + cm] = qa;
    }
}

// ---------------- edge small (edge1/2): PT=4, 1 m-tile/warp, 3 blocks/SM ------
template <int CMID, int COUT, int NITER>
__global__ __launch_bounds__(256, 3) void edge_mma_s(const __half* __restrict__ wbT,
                                                     const float* __restrict__ bb,
                                                     float* __restrict__ out) {
    constexpr int PT    = 4;
    constexpr int NT    = 64;
    constexpr int KP    = CMID + 8;
    constexpr int AROWS = PT * 32;         // 128
    constexpr int CPR8  = CMID / 8;
    extern __shared__ __align__(16) char smraw[];
    __half* As  = (__half*)smraw;               // [128][KP]
    __half* Bs  = As + AROWS * KP;              // [64][KP]
    int*   nidx = (int*)(Bs + NT * KP);         // [128]
    float* red  = (float*)(nidx + AROWS);       // [8][64]

    int tid = threadIdx.x, w = tid >> 5, lane = tid & 31;
    int p0 = blockIdx.x * PT;

    if (tid < AROWS) nidx[tid] = g_idx[p0 * K_ + tid];
    __syncthreads();

#pragma unroll
    for (int i = 0; i < AROWS * CPR8 / 256; i++) {
        int e  = i * 256 + tid;
        int r  = e / CPR8;
        int c0 = (e - r * CPR8) * 8;
        const float* qr = g_q + (size_t)nidx[r] * CMID + c0;
        const float* pr = g_p + (size_t)(p0 + (r >> 5)) * CMID + c0;
        float4 qa = *(const float4*)qr, qb = *(const float4*)(qr + 4);
        float4 pa = *(const float4*)pr, pb = *(const float4*)(pr + 4);
        uint4 pk = { pack_f16x2(lrelu(pa.x + qa.x), lrelu(pa.y + qa.y)),
                     pack_f16x2(lrelu(pa.z + qa.z), lrelu(pa.w + qa.w)),
                     pack_f16x2(lrelu(pb.x + qb.x), lrelu(pb.y + qb.y)),
                     pack_f16x2(lrelu(pb.z + qb.z), lrelu(pb.w + qb.w)) };
        *(uint4*)(As + r * KP + c0) = pk;
    }

    uint32_t aBase = smem_u32(As) +
        (uint32_t)(((w * 16 + (lane & 15)) * KP + (lane >> 4) * 8) * 2);
    uint32_t bBase = smem_u32(Bs) +
        (uint32_t)((((lane & 7) + ((lane >> 4) << 3)) * KP + ((lane >> 3) & 1) * 8) * 2);

#pragma unroll 1
    for (int it = 0; it < NITER; it++) {
        int n0 = it * NT;
        __syncthreads();
#pragma unroll
        for (int i = 0; i < NT * CPR8 / 256; i++) {
            int e  = i * 256 + tid;
            int r  = e / CPR8;
            int c0 = (e - r * CPR8) * 8;
            *(uint4*)(Bs + r * KP + c0) =
                *(const uint4*)(wbT + (size_t)(n0 + r) * CMID + c0);
        }
        __syncthreads();

        float acc[8][4];
#pragma unroll
        for (int nt = 0; nt < 8; nt++)
#pragma unroll
            for (int j = 0; j < 4; j++) acc[nt][j] = 0.f;

#pragma unroll 1
        for (int ks = 0; ks < CMID / 16; ks++) {
            uint32_t a[4];
            LDSM4(a, aBase + ks * 32);
#pragma unroll
            for (int ntp = 0; ntp < 4; ntp++) {
                uint32_t b[4];
                LDSM4(b, bBase + ntp * (16 * KP * 2) + ks * 32);
                mma16816(acc[2 * ntp],     a, b + 0);
                mma16816(acc[2 * ntp + 1], a, b + 2);
            }
        }

#pragma unroll
        for (int nt = 0; nt < 8; nt++) {
            float v0 = fmaxf(acc[nt][0], acc[nt][2]);
            float v1 = fmaxf(acc[nt][1], acc[nt][3]);
#pragma unroll
            for (int s = 4; s < 32; s <<= 1) {
                v0 = fmaxf(v0, __shfl_xor_sync(0xffffffffu, v0, s));
                v1 = fmaxf(v1, __shfl_xor_sync(0xffffffffu, v1, s));
            }
            if (lane < 4) {
                red[w * 64 + nt * 8 + 2 * lane]     = v0;
                red[w * 64 + nt * 8 + 2 * lane + 1] = v1;
            }
        }
        __syncthreads();
        {
            int pp = tid >> 6, c = tid & 63;
            float m = fmaxf(red[(2 * pp) * 64 + c], red[(2 * pp + 1) * 64 + c]);
            int col = n0 + c;
            out[(size_t)(p0 + pp) * COUT + col] = lrelu(m + bb[col]);
        }
    }
}

// ---------------- edge big (edge3): PT=8, 2 m-tiles/warp, 2 blocks/SM ---------
template <int CMID, int COUT, int NITER>
__global__ __launch_bounds__(256, 2) void edge_mma_b(const __half* __restrict__ wbT,
                                                     const float* __restrict__ bb,
                                                     float* __restrict__ out) {
    constexpr int PT    = 8;
    constexpr int NT    = 64;
    constexpr int KP    = CMID + 8;
    constexpr int AROWS = PT * 32;         // 256
    constexpr int CPR8  = CMID / 8;
    extern __shared__ __align__(16) char smraw[];
    __half* As = (__half*)smraw;                // [256][KP]
    __half* Bs = As + AROWS * KP;               // [64][KP]
    int*  nidx = (int*)(Bs + NT * KP);          // [256]

    int tid = threadIdx.x, w = tid >> 5, lane = tid & 31;
    int p0 = blockIdx.x * PT;

    nidx[tid] = g_idx[p0 * K_ + tid];
    __syncthreads();

#pragma unroll
    for (int i = 0; i < AROWS * CPR8 / 256; i++) {
        int e  = i * 256 + tid;
        int r  = e / CPR8;
        int c0 = (e - r * CPR8) * 8;
        const float* qr = g_q + (size_t)nidx[r] * CMID + c0;
        const float* pr = g_p + (size_t)(p0 + (r >> 5)) * CMID + c0;
        float4 qa = *(const float4*)qr, qb = *(const float4*)(qr + 4);
        float4 pa = *(const float4*)pr, pb = *(const float4*)(pr + 4);
        uint4 pk = { pack_f16x2(lrelu(pa.x + qa.x), lrelu(pa.y + qa.y)),
                     pack_f16x2(lrelu(pa.z + qa.z), lrelu(pa.w + qa.w)),
                     pack_f16x2(lrelu(pb.x + qb.x), lrelu(pb.y + qb.y)),
                     pack_f16x2(lrelu(pb.z + qb.z), lrelu(pb.w + qb.w)) };
        *(uint4*)(As + r * KP + c0) = pk;
    }

    uint32_t aBase = smem_u32(As) +
        (uint32_t)(((w * 32 + (lane & 15)) * KP + (lane >> 4) * 8) * 2);
    uint32_t bBase = smem_u32(Bs) +
        (uint32_t)((((lane & 7) + ((lane >> 4) << 3)) * KP + ((lane >> 3) & 1) * 8) * 2);
    int pglob = p0 + w;

#pragma unroll 1
    for (int it = 0; it < NITER; it++) {
        int n0 = it * NT;
        __syncthreads();
#pragma unroll
        for (int i = 0; i < NT * CPR8 / 256; i++) {
            int e  = i * 256 + tid;
            int r  = e / CPR8;
            int c0 = (e - r * CPR8) * 8;
            *(uint4*)(Bs + r * KP + c0) =
                *(const uint4*)(wbT + (size_t)(n0 + r) * CMID + c0);
        }
        __syncthreads();

        float acc[2][8][4];
#pragma unroll
        for (int mt = 0; mt < 2; mt++)
#pragma unroll
            for (int nt = 0; nt < 8; nt++)
#pragma unroll
                for (int j = 0; j < 4; j++) acc[mt][nt][j] = 0.f;

#pragma unroll 1
        for (int ks = 0; ks < CMID / 16; ks++) {
            uint32_t a0[4], a1[4];
            LDSM4(a0, aBase + ks * 32);
            LDSM4(a1, aBase + 16 * KP * 2 + ks * 32);
#pragma unroll
            for (int ntp = 0; ntp < 4; ntp++) {
                uint32_t b[4];
                LDSM4(b, bBase + ntp * (16 * KP * 2) + ks * 32);
                mma16816(acc[0][2 * ntp],     a0, b + 0);
                mma16816(acc[1][2 * ntp],     a1, b + 0);
                mma16816(acc[0][2 * ntp + 1], a0, b + 2);
                mma16816(acc[1][2 * ntp + 1], a1, b + 2);
            }
        }

#pragma unroll
        for (int nt = 0; nt < 8; nt++) {
            float v0 = fmaxf(fmaxf(acc[0][nt][0], acc[0][nt][2]),
                             fmaxf(acc[1][nt][0], acc[1][nt][2]));
            float v1 = fmaxf(fmaxf(acc[0][nt][1], acc[0][nt][3]),
                             fmaxf(acc[1][nt][1], acc[1][nt][3]));
#pragma unroll
            for (int s = 4; s < 32; s <<= 1) {
                v0 = fmaxf(v0, __shfl_xor_sync(0xffffffffu, v0, s));
                v1 = fmaxf(v1, __shfl_xor_sync(0xffffffffu, v1, s));
            }
            if (lane < 4) {
                int col = n0 + nt * 8 + 2 * lane;
                out[(size_t)pglob * COUT + col]     = lrelu(v0 + bb[col]);
                out[(size_t)pglob * COUT + col + 1] = lrelu(v1 + bb[col + 1]);
            }
        }
    }
}

// ---------------- head1: concat(704) -> 512 via f16 mma, lrelu, h1 f16 --------
__global__ __launch_bounds__(256, 2) void head1_mma(const __half* __restrict__ wT,
                                                    const float* __restrict__ bias) {
    __shared__ __align__(16) __half As[64 * 72];
    __shared__ __align__(16) __half Bs[128 * 72];
    int tid = threadIdx.x, w = tid >> 5, lane = tid & 31;
    int m0 = blockIdx.x * 64, n0 = blockIdx.y * 128;
    int mt = (w >> 1) * 16, ng = (w & 1) * 64;

    float acc[8][4];
#pragma unroll
    for (int nt = 0; nt < 8; nt++)
#pragma unroll
        for (int j = 0; j < 4; j++) acc[nt][j] = 0.f;

    uint32_t aBase = smem_u32(As) +
        (uint32_t)(((mt + (lane & 15)) * 72 + (lane >> 4) * 8) * 2);
    uint32_t bBase = smem_u32(Bs) +
        (uint32_t)(((ng + (lane & 7) + ((lane >> 4) << 3)) * 72 + ((lane >> 3) & 1) * 8) * 2);

#pragma unroll 1
    for (int kc = 0; kc < 11; kc++) {
        const float* src; int stride, off;
        if (kc == 0)      { src = g_x1; stride = 64;  off = 0; }
        else if (kc <= 2) { src = g_x2; stride = 128; off = (kc - 1) * 64; }
        else              { src = g_x3; stride = 512; off = (kc - 3) * 64; }
#pragma unroll
        for (int i = 0; i < 2; i++) {
            int t = i * 256 + tid;
            int r = t >> 3, c0 = (t & 7) * 8;
            const float* sp = src + (size_t)(m0 + r) * stride + off + c0;
            float4 a = *(const float4*)sp, b = *(const float4*)(sp + 4);
            uint4 pk = { pack_f16x2(a.x, a.y), pack_f16x2(a.z, a.w),
                         pack_f16x2(b.x, b.y), pack_f16x2(b.z, b.w) };
            *(uint4*)(As + r * 72 + c0) = pk;
        }
#pragma unroll
        for (int i = 0; i < 4; i++) {
            int t = i * 256 + tid;
            int r = t >> 3, c0 = (t & 7) * 8;
            *(uint4*)(Bs + r * 72 + c0) =
                *(const uint4*)(wT + (size_t)(n0 + r) * 704 + kc * 64 + c0);
        }
        __syncthreads();
#pragma unroll
        for (int ks = 0; ks < 4; ks++) {
            uint32_t a[4];
            LDSM4(a, aBase + ks * 32);
#pragma unroll
            for (int ntp = 0; ntp < 4; ntp++) {
                uint32_t b[4];
                LDSM4(b, bBase + ntp * (16 * 72 * 2) + ks * 32);
                mma16816(acc[2 * ntp],     a, b + 0);
                mma16816(acc[2 * ntp + 1], a, b + 2);
            }
        }
        __syncthreads();
    }

    int gid = lane >> 2, tig = lane & 3;
    int row = m0 + mt + gid;
#pragma unroll
    for (int nt = 0; nt < 8; nt++) {
        int col = n0 + ng + nt * 8 + 2 * tig;
        float b0 = bias[col], b1 = bias[col + 1];
        *(uint32_t*)(g_h1 + (size_t)row * 512 + col) =
            pack_f16x2(lrelu(acc[nt][0] + b0), lrelu(acc[nt][1] + b1));
        *(uint32_t*)(g_h1 + (size_t)(row + 8) * 512 + col) =
            pack_f16x2(lrelu(acc[nt][2] + b0), lrelu(acc[nt][3] + b1));
    }
}

// ---------------- head2: 512 -> 256 via f16 mma, lrelu, h2 fp32 ---------------
__global__ __launch_bounds__(256, 2) void head2_mma(const __half* __restrict__ wT,
                                                    const float* __restrict__ bias) {
    __shared__ __align__(16) __half As[64 * 72];
    __shared__ __align__(16) __half Bs[128 * 72];
    int tid = threadIdx.x, w = tid >> 5, lane = tid & 31;
    int m0 = blockIdx.x * 64, n0 = blockIdx.y * 128;
    int mt = (w >> 1) * 16, ng = (w & 1) * 64;

    float acc[8][4];
#pragma unroll
    for (int nt = 0; nt < 8; nt++)
#pragma unroll
        for (int j = 0; j < 4; j++) acc[nt][j] = 0.f;

    uint32_t aBase = smem_u32(As) +
        (uint32_t)(((mt + (lane & 15)) * 72 + (lane >> 4) * 8) * 2);
    uint32_t bBase = smem_u32(Bs) +
        (uint32_t)(((ng + (lane & 7) + ((lane >> 4) << 3)) * 72 + ((lane >> 3) & 1) * 8) * 2);

#pragma unroll 1
    for (int kc = 0; kc < 8; kc++) {
#pragma unroll
        for (int i = 0; i < 2; i++) {
            int t = i * 256 + tid;
            int r = t >> 3, c0 = (t & 7) * 8;
            *(uint4*)(As + r * 72 + c0) =
                *(const uint4*)(g_h1 + (size_t)(m0 + r) * 512 + kc * 64 + c0);
        }
#pragma unroll
        for (int i = 0; i < 4; i++) {
            int t = i * 256 + tid;
            int r = t >> 3, c0 = (t & 7) * 8;
            *(uint4*)(Bs + r * 72 + c0) =
                *(const uint4*)(wT + (size_t)(n0 + r) * 512 + kc * 64 + c0);
        }
        __syncthreads();
#pragma unroll
        for (int ks = 0; ks < 4; ks++) {
            uint32_t a[4];
            LDSM4(a, aBase + ks * 32);
#pragma unroll
            for (int ntp = 0; ntp < 4; ntp++) {
                uint32_t b[4];
                LDSM4(b, bBase + ntp * (16 * 72 * 2) + ks * 32);
                mma16816(acc[2 * ntp],     a, b + 0);
                mma16816(acc[2 * ntp + 1], a, b + 2);
            }
        }
        __syncthreads();
    }

    int gid = lane >> 2, tig = lane & 3;
    int row = m0 + mt + gid;
#pragma unroll
    for (int nt = 0; nt < 8; nt++) {
        int col = n0 + ng + nt * 8 + 2 * tig;
        float b0 = bias[col], b1 = bias[col + 1];
        g_h2[(size_t)row * 256 + col]           = lrelu(acc[nt][0] + b0);
        g_h2[(size_t)row * 256 + col + 1]       = lrelu(acc[nt][1] + b1);
        g_h2[(size_t)(row + 8) * 256 + col]     = lrelu(acc[nt][2] + b0);
        g_h2[(size_t)(row + 8) * 256 + col + 1] = lrelu(acc[nt][3] + b1);
    }
}

// ---------------- head3: 256 -> 12 (fp32, no lrelu) ----------------
__global__ __launch_bounds__(192) void head3_kernel(const float* __restrict__ wf3,
                                                    const float* __restrict__ bf3,
                                                    float* __restrict__ out) {
    int blk = blockIdx.x, tid = threadIdx.x;
    int r = tid / 12, c = tid - r * 12;
    int row = blk * 16 + r;
    const float* h = g_h2 + (size_t)row * 256;
    float a0 = bf3[c], a1 = 0.f, a2 = 0.f, a3 = 0.f;
#pragma unroll 4
    for (int cm = 0; cm < 256; cm += 4) {
        a0 = fmaf(h[cm + 0], wf3[(cm + 0) * 12 + c], a0);
        a1 = fmaf(h[cm + 1], wf3[(cm + 1) * 12 + c], a1);
        a2 = fmaf(h[cm + 2], wf3[(cm + 2) * 12 + c], a2);
        a3 = fmaf(h[cm + 3], wf3[(cm + 3) * 12 + c], a3);
    }
    out[(size_t)row * 12 + c] = (a0 + a1) + (a2 + a3);
}

// ---------------- launch ----------------
constexpr int SMEM_P1 = (2 * 64 * 4 + 32 * 4 + 64) * 4;
constexpr int SMEM_P2 = (2 * 64 * 68 + 32 * 68 + 64) * 4;
constexpr int SMEM_P3 = (2 * 128 * 132 + 32 * 132 + 128) * 4;
constexpr int SMEM_ES = (128 * 72 + 64 * 72) * 2 + 128 * 4 + 8 * 64 * 4;  // 30208
constexpr int SMEM_EB = (256 * 136 + 64 * 136) * 2 + 256 * 4;             // 88064

extern "C" void kernel_launch(void* const* d_in, const int* in_sizes, int n_in,
                              void* d_out, int out_size) {
    const float* x   = (const float*)d_in[0];
    const float* pos = (const float*)d_in[1];
    const float* w1a = (const float*)d_in[2];
    const float* b1a = (const float*)d_in[3];
    const float* w1b = (const float*)d_in[4];
    const float* b1b = (const float*)d_in[5];
    const float* w2a = (const float*)d_in[6];
    const float* b2a = (const float*)d_in[7];
    const float* w2b = (const float*)d_in[8];
    const float* b2b = (const float*)d_in[9];
    const float* w3a = (const float*)d_in[10];
    const float* b3a = (const float*)d_in[11];
    const float* w3b = (const float*)d_in[12];
    const float* b3b = (const float*)d_in[13];
    const float* wf1 = (const float*)d_in[14];
    const float* bf1 = (const float*)d_in[15];
    const float* wf2 = (const float*)d_in[16];
    const float* bf2 = (const float*)d_in[17];
    const float* wf3 = (const float*)d_in[18];
    const float* bf3 = (const float*)d_in[19];
    float* out = (float*)d_out;

    float *x1p, *x2p, *x3p;
    __half *wt1p, *wt2p, *wt3p, *wf1Tp, *wf2Tp;
    cudaGetSymbolAddress((void**)&x1p, g_x1);
    cudaGetSymbolAddress((void**)&x2p, g_x2);
    cudaGetSymbolAddress((void**)&x3p, g_x3);
    cudaGetSymbolAddress((void**)&wt1p, g_wbT1);
    cudaGetSymbolAddress((void**)&wt2p, g_wbT2);
    cudaGetSymbolAddress((void**)&wt3p, g_wbT3);
    cudaGetSymbolAddress((void**)&wf1Tp, g_wf1T);
    cudaGetSymbolAddress((void**)&wf2Tp, g_wf2T);

    static bool attr_done = false;
    if (!attr_done) {
        cudaFuncSetAttribute(proj_kernel<128, 128, 132>,
                             cudaFuncAttributeMaxDynamicSharedMemorySize, SMEM_P3);
        cudaFuncSetAttribute(edge_mma_s<64, 64, 1>,
                             cudaFuncAttributeMaxDynamicSharedMemorySize, SMEM_ES);
        cudaFuncSetAttribute(edge_mma_s<64, 128, 2>,
                             cudaFuncAttributeMaxDynamicSharedMemorySize, SMEM_ES);
        cudaFuncSetAttribute(edge_mma_b<128, 512, 8>,
                             cudaFuncAttributeMaxDynamicSharedMemorySize, SMEM_EB);
        attr_done = true;
    }

    prep_misc<<<368, 256>>>(pos, w1b, w2b, w3b, wt1p, wt2p, wt3p);         // 1
    knn_kernel<<<BN_, 256>>>();                                            // 2
    proj_kernel<3, 64, 4><<<BN_ / 32, 256, SMEM_P1>>>(x, w1a, b1a);        // 3
    edge_mma_s<64, 64, 1><<<BN_ / 4, 256, SMEM_ES>>>(wt1p, b1b, x1p);      // 4 <- ncu
    prep_wf<<<1920, 256>>>(wf1, wf2, wf1Tp, wf2Tp);                        // 5

    // block2: 64 -> 64 -> 128
    proj_kernel<64, 64, 68><<<BN_ / 32, 256, SMEM_P2>>>(x1p, w2a, b2a);
    edge_mma_s<64, 128, 2><<<BN_ / 4, 256, SMEM_ES>>>(wt2p, b2b, x2p);
    // block3: 128 -> 128 -> 512
    proj_kernel<128, 128, 132><<<BN_ / 32, 256, SMEM_P3>>>(x2p, w3a, b3a);
    edge_mma_b<128, 512, 8><<<BN_ / 8, 256, SMEM_EB>>>(wt3p, b3b, x3p);

    // head: 704 -> 512 (f16 mma) -> 256 (f16 mma) -> 12 (fp32)
    head1_mma<<<dim3(BN_ / 64, 4), 256>>>(wf1Tp, bf1);
    head2_mma<<<dim3(BN_ / 64, 2), 256>>>(wf2Tp, bf2);
    head3_kernel<<<BN_ / 16, 192>>>(wf3, bf3, out);
}

// round 15
// speedup vs baseline: 1.1702x; 1.0627x over previous
#include <cuda_runtime.h>
#include <cuda_fp16.h>
#include <cstdint>

// DGCNN: B=8, N=2048, k=32.  (sm_103 PTX target -> mma.sync f16 + ldmatrix)
// prep_misc -> knn -> proj1 -> edge1 -> prep_wf -> [proj,edge]x2 -> heads.
// R15: heads (256,3); edge2 back to PT=8 (256,2); proj3 cin-chunked weights
// (87KB dyn smem -> 2 blocks/SM, bit-identical accumulation order).

#define NEG 0.2f
constexpr int B_  = 8;
constexpr int N_  = 2048;
constexpr int BN_ = B_ * N_;   // 16384
constexpr int K_  = 32;

// ---- scratch (device globals; no runtime allocation allowed) ----
__device__ float4 g_pos4[BN_];
__device__ int    g_idx[BN_ * K_];
__device__ float  g_p[BN_ * 128];
__device__ float  g_q[BN_ * 128];
__device__ float  g_x1[BN_ * 64];
__device__ float  g_x2[BN_ * 128];
__device__ float  g_x3[BN_ * 512];
__device__ __half g_h1[BN_ * 512];
__device__ float  g_h2[BN_ * 256];
__device__ __half g_wbT1[64 * 64];
__device__ __half g_wbT2[128 * 64];
__device__ __half g_wbT3[512 * 128];
__device__ __half g_wf1T[512 * 704];
__device__ __half g_wf2T[256 * 512];

__device__ __forceinline__ float lrelu(float v) { return v >= 0.f ? v : NEG * v; }

__device__ __forceinline__ uint32_t pack_f16x2(float lo, float hi) {
    uint32_t u;
    asm("cvt.rn.f16x2.f32 %0, %1, %2;" : "=r"(u) : "f"(hi), "f"(lo));
    return u;
}

__device__ __forceinline__ uint32_t smem_u32(const void* p) {
    uint32_t a;
    asm("{ .reg .u64 t; cvta.to.shared.u64 t, %1; cvt.u32.u64 %0, t; }" : "=r"(a) : "l"(p));
    return a;
}

__device__ __forceinline__ void mma16816(float d[4], const uint32_t a[4],
                                         const uint32_t b[2]) {
    asm volatile(
        "mma.sync.aligned.m16n8k16.row.col.f32.f16.f16.f32 "
        "{%0,%1,%2,%3}, {%4,%5,%6,%7}, {%8,%9}, {%0,%1,%2,%3};\n"
        : "+f"(d[0]), "+f"(d[1]), "+f"(d[2]), "+f"(d[3])
        : "r"(a[0]), "r"(a[1]), "r"(a[2]), "r"(a[3]), "r"(b[0]), "r"(b[1]));
}

#define LDSM4(r, addr) \
    asm volatile("ldmatrix.sync.aligned.m8n8.x4.shared.b16 {%0,%1,%2,%3}, [%4];" \
                 : "=r"((r)[0]), "=r"((r)[1]), "=r"((r)[2]), "=r"((r)[3]) \
                 : "r"(addr))

// ---------------- prep: pos4 (xyz + sq) + edge-weight transposes ----------------
__global__ void prep_misc(const float* __restrict__ pos,
                          const float* __restrict__ w1, const float* __restrict__ w2,
                          const float* __restrict__ w3, __half* __restrict__ t1,
                          __half* __restrict__ t2, __half* __restrict__ t3) {
    int t = blockIdx.x * 256 + threadIdx.x;
    if (t < BN_) {
        float x = pos[t * 3 + 0], y = pos[t * 3 + 1], z = pos[t * 3 + 2];
        g_pos4[t] = make_float4(x, y, z, fmaf(z, z, fmaf(y, y, x * x)));
    } else if (t < BN_ + 4096) {
        int e = t - BN_;
        int k = e >> 6, n = e & 63;
        t1[n * 64 + k] = __float2half_rn(w1[e]);
    } else if (t < BN_ + 12288) {
        int e = t - BN_ - 4096;
        int k = e >> 7, n = e & 127;
        t2[n * 64 + k] = __float2half_rn(w2[e]);
    } else if (t < BN_ + 77824) {
        int e = t - BN_ - 12288;
        int k = e >> 9, n = e & 511;
        t3[n * 128 + k] = __float2half_rn(w3[e]);
    }
}

// ---------------- head-weight transpose + f16 ----------------
__global__ void prep_wf(const float* __restrict__ wf1, const float* __restrict__ wf2,
                        __half* __restrict__ t1, __half* __restrict__ t2) {
    int t = blockIdx.x * 256 + threadIdx.x;
    if (t < 360448) {
        int n = t / 704, k = t - n * 704;
        t1[t] = __float2half_rn(wf1[k * 512 + n]);
    } else {
        int e = t - 360448;
        int n = e >> 9, k = e & 511;
        t2[e] = __float2half_rn(wf2[k * 256 + n]);
    }
}

// ---------------- kNN: REDUX + sorted-pop selection (pos4 distances) ----------
#define KCE(a, b) { \
    bool sw = (khi[a] > khi[b]) || (khi[a] == khi[b] && klo[a] > klo[b]); \
    unsigned th = sw ? khi[b] : khi[a], tl = sw ? klo[b] : klo[a]; \
    khi[b] = sw ? khi[a] : khi[b]; klo[b] = sw ? klo[a] : klo[b]; \
    khi[a] = th; klo[a] = tl; }
#define KSORT8() \
    KCE(0,1) KCE(2,3) KCE(4,5) KCE(6,7) \
    KCE(0,2) KCE(1,3) KCE(4,6) KCE(5,7) \
    KCE(1,2) KCE(5,6) \
    KCE(0,4) KCE(1,5) KCE(2,6) KCE(3,7) \
    KCE(2,4) KCE(3,5) \
    KCE(1,2) KCE(3,4) KCE(5,6)

__global__ __launch_bounds__(256) void knn_kernel() {
    __shared__ unsigned long long cand[256];
    int point = blockIdx.x;
    int base  = (point >> 11) * N_;
    int tid   = threadIdx.x;
    int w     = tid >> 5, lane = tid & 31;

    float4 pq = g_pos4[point];
    float sqn = pq.w;

    {
        unsigned khi[8], klo[8];
#pragma unroll
        for (int i = 0; i < 8; i++) {
            int m = (w << 8) + (i << 5) + lane;
            float4 pm = g_pos4[base + m];
            float dot = fmaf(pq.z, pm.z, fmaf(pq.y, pm.y, pq.x * pm.x));
            float d2  = (sqn - 2.f * dot) + pm.w;
            unsigned u = __float_as_uint(d2);
            khi[i] = (u & 0x80000000u) ? ~u : (u | 0x80000000u);
            klo[i] = (unsigned)m;
        }
        KSORT8();

#pragma unroll 4
        for (int it = 0; it < K_; it++) {
            unsigned mhi  = __reduce_min_sync(0xffffffffu, khi[0]);
            unsigned prop = (khi[0] == mhi) ? klo[0] : 0xFFFFFFFFu;
            unsigned mlo  = __reduce_min_sync(0xffffffffu, prop);
            if (lane == 0)
                cand[(w << 5) + it] = ((unsigned long long)mhi << 32) | mlo;
            if (prop == mlo) {
#pragma unroll
                for (int i = 0; i < 7; i++) { khi[i] = khi[i + 1]; klo[i] = klo[i + 1]; }
                khi[7] = 0xFFFFFFFFu; klo[7] = 0xFFFFFFFFu;
            }
        }
    }
    __syncthreads();

    if (w == 0) {
        unsigned khi[8], klo[8];
#pragma unroll
        for (int i = 0; i < 8; i++) {
            unsigned long long c = cand[(i << 5) + lane];
            khi[i] = (unsigned)(c >> 32);
            klo[i] = (unsigned)c;
        }
        KSORT8();

#pragma unroll 4
        for (int it = 0; it < K_; it++) {
            unsigned mhi  = __reduce_min_sync(0xffffffffu, khi[0]);
            unsigned prop = (khi[0] == mhi) ? klo[0] : 0xFFFFFFFFu;
            unsigned mlo  = __reduce_min_sync(0xffffffffu, prop);
            if (lane == 0) g_idx[point * K_ + it] = base + (int)mlo;
            if (prop == mlo) {
#pragma unroll
                for (int i = 0; i < 7; i++) { khi[i] = khi[i + 1]; klo[i] = klo[i + 1]; }
                khi[7] = 0xFFFFFFFFu; klo[7] = 0xFFFFFFFFu;
            }
        }
    }
}

// ---------------- batched per-point projections p,q (proj1/proj2) ------------
template <int CIN, int CMID, int CINP>
__global__ __launch_bounds__(256) void proj_kernel(const float* __restrict__ x,
                                                   const float* __restrict__ wa,
                                                   const float* __restrict__ ba) {
    extern __shared__ __align__(16) float smf[];
    float* wts = smf;
    float* wqs = wts + CMID * CINP;
    float* xs  = wqs + CMID * CINP;
    float* bas = xs + 32 * CINP;
    int tid = threadIdx.x;
    int p0  = blockIdx.x * 32;

    for (int t = tid; t < CIN * CMID; t += 256) {
        int ci = t / CMID, cm = t - ci * CMID;
        float top = wa[t], bot = wa[CIN * CMID + t];
        wts[cm * CINP + ci] = top - bot;
        wqs[cm * CINP + ci] = bot;
    }
    for (int t = tid; t < 32 * CIN; t += 256) {
        int pp = t / CIN, ci = t - pp * CIN;
        xs[pp * CINP + ci] = x[(size_t)(p0 + pp) * CIN + ci];
    }
    if (tid < CMID) bas[tid] = ba[tid];
    __syncthreads();

    constexpr int LANES = 256 / CMID;
    int li = tid / CMID, cm = tid - li * CMID;
    const float* wtr = wts + cm * CINP;
    const float* wqr = wqs + cm * CINP;
    float bias = bas[cm];

    for (int pp = li; pp < 32; pp += LANES) {
        const float* xr = xs + pp * CINP;
        float pa = bias, qa = 0.f;
        if constexpr (CIN % 4 == 0) {
#pragma unroll
            for (int ci = 0; ci < CIN; ci += 4) {
                float4 xv = *(const float4*)(xr + ci);
                float4 wt4 = *(const float4*)(wtr + ci);
                float4 wq4 = *(const float4*)(wqr + ci);
                pa = fmaf(xv.x, wt4.x, pa); qa = fmaf(xv.x, wq4.x, qa);
                pa = fmaf(xv.y, wt4.y, pa); qa = fmaf(xv.y, wq4.y, qa);
                pa = fmaf(xv.z, wt4.z, pa); qa = fmaf(xv.z, wq4.z, qa);
                pa = fmaf(xv.w, wt4.w, pa); qa = fmaf(xv.w, wq4.w, qa);
            }
        } else {
#pragma unroll
            for (int ci = 0; ci < CIN; ci++) {
                float xv = xr[ci];
                pa = fmaf(xv, wtr[ci], pa);
                qa = fmaf(xv, wqr[ci], qa);
            }
        }
        g_p[(size_t)(p0 + pp) * CMID + cm] = pa;
        g_q[(size_t)(p0 + pp) * CMID + cm] = qa;
    }
}

// ---------------- proj3 (128 -> 128): cin-chunked weights, 2 blocks/SM --------
// Same per-point ci-ascending accumulation order as proj_kernel -> bit-identical.
__global__ __launch_bounds__(256, 2) void proj3_kernel(const float* __restrict__ x,
                                                       const float* __restrict__ wa,
                                                       const float* __restrict__ ba) {
    constexpr int CIN = 128, CMID = 128, CH = 64, CHP = 68, XSP = 132;
    extern __shared__ __align__(16) float smf[];
    float* wts = smf;                       // [CMID][CHP]
    float* wqs = wts + CMID * CHP;          // [CMID][CHP]
    float* xs  = wqs + CMID * CHP;          // [32][XSP]
    float* bas = xs + 32 * XSP;             // [CMID]
    int tid = threadIdx.x;
    int p0  = blockIdx.x * 32;

    for (int t = tid; t < 32 * CIN; t += 256) {
        int pp = t >> 7, ci = t & 127;
        xs[pp * XSP + ci] = x[(size_t)(p0 + pp) * CIN + ci];
    }
    if (tid < CMID) bas[tid] = ba[tid];

    int li = tid >> 7, cm = tid & 127;      // LANES=2
    float pa[16], qa[16];
#pragma unroll
    for (int j = 0; j < 16; j++) { pa[j] = bas[cm]; qa[j] = 0.f; }
    // NOTE: bas[cm] read before sync is fine only if written; guard with sync:
    __syncthreads();
#pragma unroll
    for (int j = 0; j < 16; j++) pa[j] = bas[cm];

#pragma unroll 1
    for (int ch = 0; ch < 2; ch++) {
        int c0 = ch * CH;
        if (ch) __syncthreads();            // drain reads of previous chunk
        for (int t = tid; t < CH * CMID; t += 256) {
            int cil = t >> 7, cmw = t & 127;
            int ci = c0 + cil;
            float top = wa[ci * CMID + cmw];
            float bot = wa[(ci + CIN) * CMID + cmw];
            wts[cmw * CHP + cil] = top - bot;
            wqs[cmw * CHP + cil] = bot;
        }
        __syncthreads();

        const float* wtr = wts + cm * CHP;
        const float* wqr = wqs + cm * CHP;
#pragma unroll
        for (int j = 0; j < 16; j++) {
            const float* xr = xs + (li + j * 2) * XSP + c0;
            float p = pa[j], q = qa[j];
#pragma unroll
            for (int ci = 0; ci < CH; ci += 4) {
                float4 xv = *(const float4*)(xr + ci);
                float4 wt4 = *(const float4*)(wtr + ci);
                float4 wq4 = *(const float4*)(wqr + ci);
                p = fmaf(xv.x, wt4.x, p); q = fmaf(xv.x, wq4.x, q);
                p = fmaf(xv.y, wt4.y, p); q = fmaf(xv.y, wq4.y, q);
                p = fmaf(xv.z, wt4.z, p); q = fmaf(xv.z, wq4.z, q);
                p = fmaf(xv.w, wt4.w, p); q = fmaf(xv.w, wq4.w, q);
            }
            pa[j] = p; qa[j] = q;
        }
    }
#pragma unroll
    for (int j = 0; j < 16; j++) {
        g_p[(size_t)(p0 + li + j * 2) * CMID + cm] = pa[j];
        g_q[(size_t)(p0 + li + j * 2) * CMID + cm] = qa[j];
    }
}

// ---------------- edge small (edge1): PT=4, 1 m-tile/warp, 3 blocks/SM --------
template <int CMID, int COUT, int NITER>
__global__ __launch_bounds__(256, 3) void edge_mma_s(const __half* __restrict__ wbT,
                                                     const float* __restrict__ bb,
                                                     float* __restrict__ out) {
    constexpr int PT    = 4;
    constexpr int NT    = 64;
    constexpr int KP    = CMID + 8;
    constexpr int AROWS = PT * 32;         // 128
    constexpr int CPR8  = CMID / 8;
    extern __shared__ __align__(16) char smraw[];
    __half* As  = (__half*)smraw;
    __half* Bs  = As + AROWS * KP;
    int*   nidx = (int*)(Bs + NT * KP);
    float* red  = (float*)(nidx + AROWS);

    int tid = threadIdx.x, w = tid >> 5, lane = tid & 31;
    int p0 = blockIdx.x * PT;

    if (tid < AROWS) nidx[tid] = g_idx[p0 * K_ + tid];
    __syncthreads();

#pragma unroll
    for (int i = 0; i < AROWS * CPR8 / 256; i++) {
        int e  = i * 256 + tid;
        int r  = e / CPR8;
        int c0 = (e - r * CPR8) * 8;
        const float* qr = g_q + (size_t)nidx[r] * CMID + c0;
        const float* pr = g_p + (size_t)(p0 + (r >> 5)) * CMID + c0;
        float4 qa = *(const float4*)qr, qb = *(const float4*)(qr + 4);
        float4 pa = *(const float4*)pr, pb = *(const float4*)(pr + 4);
        uint4 pk = { pack_f16x2(lrelu(pa.x + qa.x), lrelu(pa.y + qa.y)),
                     pack_f16x2(lrelu(pa.z + qa.z), lrelu(pa.w + qa.w)),
                     pack_f16x2(lrelu(pb.x + qb.x), lrelu(pb.y + qb.y)),
                     pack_f16x2(lrelu(pb.z + qb.z), lrelu(pb.w + qb.w)) };
        *(uint4*)(As + r * KP + c0) = pk;
    }

    uint32_t aBase = smem_u32(As) +
        (uint32_t)(((w * 16 + (lane & 15)) * KP + (lane >> 4) * 8) * 2);
    uint32_t bBase = smem_u32(Bs) +
        (uint32_t)((((lane & 7) + ((lane >> 4) << 3)) * KP + ((lane >> 3) & 1) * 8) * 2);

#pragma unroll 1
    for (int it = 0; it < NITER; it++) {
        int n0 = it * NT;
        __syncthreads();
#pragma unroll
        for (int i = 0; i < NT * CPR8 / 256; i++) {
            int e  = i * 256 + tid;
            int r  = e / CPR8;
            int c0 = (e - r * CPR8) * 8;
            *(uint4*)(Bs + r * KP + c0) =
                *(const uint4*)(wbT + (size_t)(n0 + r) * CMID + c0);
        }
        __syncthreads();

        float acc[8][4];
#pragma unroll
        for (int nt = 0; nt < 8; nt++)
#pragma unroll
            for (int j = 0; j < 4; j++) acc[nt][j] = 0.f;

#pragma unroll 1
        for (int ks = 0; ks < CMID / 16; ks++) {
            uint32_t a[4];
            LDSM4(a, aBase + ks * 32);
#pragma unroll
            for (int ntp = 0; ntp < 4; ntp++) {
                uint32_t b[4];
                LDSM4(b, bBase + ntp * (16 * KP * 2) + ks * 32);
                mma16816(acc[2 * ntp],     a, b + 0);
                mma16816(acc[2 * ntp + 1], a, b + 2);
            }
        }

#pragma unroll
        for (int nt = 0; nt < 8; nt++) {
            float v0 = fmaxf(acc[nt][0], acc[nt][2]);
            float v1 = fmaxf(acc[nt][1], acc[nt][3]);
#pragma unroll
            for (int s = 4; s < 32; s <<= 1) {
                v0 = fmaxf(v0, __shfl_xor_sync(0xffffffffu, v0, s));
                v1 = fmaxf(v1, __shfl_xor_sync(0xffffffffu, v1, s));
            }
            if (lane < 4) {
                red[w * 64 + nt * 8 + 2 * lane]     = v0;
                red[w * 64 + nt * 8 + 2 * lane + 1] = v1;
            }
        }
        __syncthreads();
        {
            int pp = tid >> 6, c = tid & 63;
            float m = fmaxf(red[(2 * pp) * 64 + c], red[(2 * pp + 1) * 64 + c]);
            int col = n0 + c;
            out[(size_t)(p0 + pp) * COUT + col] = lrelu(m + bb[col]);
        }
    }
}

// ---------------- edge big (edge2/edge3): PT=8, 2 m-tiles/warp, 2 blocks/SM ---
template <int CMID, int COUT, int NITER>
__global__ __launch_bounds__(256, 2) void edge_mma_b(const __half* __restrict__ wbT,
                                                     const float* __restrict__ bb,
                                                     float* __restrict__ out) {
    constexpr int PT    = 8;
    constexpr int NT    = 64;
    constexpr int KP    = CMID + 8;
    constexpr int AROWS = PT * 32;         // 256
    constexpr int CPR8  = CMID / 8;
    extern __shared__ __align__(16) char smraw[];
    __half* As = (__half*)smraw;
    __half* Bs = As + AROWS * KP;
    int*  nidx = (int*)(Bs + NT * KP);

    int tid = threadIdx.x, w = tid >> 5, lane = tid & 31;
    int p0 = blockIdx.x * PT;

    nidx[tid] = g_idx[p0 * K_ + tid];
    __syncthreads();

#pragma unroll
    for (int i = 0; i < AROWS * CPR8 / 256; i++) {
        int e  = i * 256 + tid;
        int r  = e / CPR8;
        int c0 = (e - r * CPR8) * 8;
        const float* qr = g_q + (size_t)nidx[r] * CMID + c0;
        const float* pr = g_p + (size_t)(p0 + (r >> 5)) * CMID + c0;
        float4 qa = *(const float4*)qr, qb = *(const float4*)(qr + 4);
        float4 pa = *(const float4*)pr, pb = *(const float4*)(pr + 4);
        uint4 pk = { pack_f16x2(lrelu(pa.x + qa.x), lrelu(pa.y + qa.y)),
                     pack_f16x2(lrelu(pa.z + qa.z), lrelu(pa.w + qa.w)),
                     pack_f16x2(lrelu(pb.x + qb.x), lrelu(pb.y + qb.y)),
                     pack_f16x2(lrelu(pb.z + qb.z), lrelu(pb.w + qb.w)) };
        *(uint4*)(As + r * KP + c0) = pk;
    }

    uint32_t aBase = smem_u32(As) +
        (uint32_t)(((w * 32 + (lane & 15)) * KP + (lane >> 4) * 8) * 2);
    uint32_t bBase = smem_u32(Bs) +
        (uint32_t)((((lane & 7) + ((lane >> 4) << 3)) * KP + ((lane >> 3) & 1) * 8) * 2);
    int pglob = p0 + w;

#pragma unroll 1
    for (int it = 0; it < NITER; it++) {
        int n0 = it * NT;
        __syncthreads();
#pragma unroll
        for (int i = 0; i < NT * CPR8 / 256; i++) {
            int e  = i * 256 + tid;
            int r  = e / CPR8;
            int c0 = (e - r * CPR8) * 8;
            *(uint4*)(Bs + r * KP + c0) =
                *(const uint4*)(wbT + (size_t)(n0 + r) * CMID + c0);
        }
        __syncthreads();

        float acc[2][8][4];
#pragma unroll
        for (int mt = 0; mt < 2; mt++)
#pragma unroll
            for (int nt = 0; nt < 8; nt++)
#pragma unroll
                for (int j = 0; j < 4; j++) acc[mt][nt][j] = 0.f;

#pragma unroll 1
        for (int ks = 0; ks < CMID / 16; ks++) {
            uint32_t a0[4], a1[4];
            LDSM4(a0, aBase + ks * 32);
            LDSM4(a1, aBase + 16 * KP * 2 + ks * 32);
#pragma unroll
            for (int ntp = 0; ntp < 4; ntp++) {
                uint32_t b[4];
                LDSM4(b, bBase + ntp * (16 * KP * 2) + ks * 32);
                mma16816(acc[0][2 * ntp],     a0, b + 0);
                mma16816(acc[1][2 * ntp],     a1, b + 0);
                mma16816(acc[0][2 * ntp + 1], a0, b + 2);
                mma16816(acc[1][2 * ntp + 1], a1, b + 2);
            }
        }

#pragma unroll
        for (int nt = 0; nt < 8; nt++) {
            float v0 = fmaxf(fmaxf(acc[0][nt][0], acc[0][nt][2]),
                             fmaxf(acc[1][nt][0], acc[1][nt][2]));
            float v1 = fmaxf(fmaxf(acc[0][nt][1], acc[0][nt][3]),
                             fmaxf(acc[1][nt][1], acc[1][nt][3]));
#pragma unroll
            for (int s = 4; s < 32; s <<= 1) {
                v0 = fmaxf(v0, __shfl_xor_sync(0xffffffffu, v0, s));
                v1 = fmaxf(v1, __shfl_xor_sync(0xffffffffu, v1, s));
            }
            if (lane < 4) {
                int col = n0 + nt * 8 + 2 * lane;
                out[(size_t)pglob * COUT + col]     = lrelu(v0 + bb[col]);
                out[(size_t)pglob * COUT + col + 1] = lrelu(v1 + bb[col + 1]);
            }
        }
    }
}

// ---------------- head1: concat(704) -> 512 via f16 mma, lrelu, h1 f16 --------
__global__ __launch_bounds__(256, 3) void head1_mma(const __half* __restrict__ wT,
                                                    const float* __restrict__ bias) {
    __shared__ __align__(16) __half As[64 * 72];
    __shared__ __align__(16) __half Bs[128 * 72];
    int tid = threadIdx.x, w = tid >> 5, lane = tid & 31;
    int m0 = blockIdx.x * 64, n0 = blockIdx.y * 128;
    int mt = (w >> 1) * 16, ng = (w & 1) * 64;

    float acc[8][4];
#pragma unroll
    for (int nt = 0; nt < 8; nt++)
#pragma unroll
        for (int j = 0; j < 4; j++) acc[nt][j] = 0.f;

    uint32_t aBase = smem_u32(As) +
        (uint32_t)(((mt + (lane & 15)) * 72 + (lane >> 4) * 8) * 2);
    uint32_t bBase = smem_u32(Bs) +
        (uint32_t)(((ng + (lane & 7) + ((lane >> 4) << 3)) * 72 + ((lane >> 3) & 1) * 8) * 2);

#pragma unroll 1
    for (int kc = 0; kc < 11; kc++) {
        const float* src; int stride, off;
        if (kc == 0)      { src = g_x1; stride = 64;  off = 0; }
        else if (kc <= 2) { src = g_x2; stride = 128; off = (kc - 1) * 64; }
        else              { src = g_x3; stride = 512; off = (kc - 3) * 64; }
#pragma unroll
        for (int i = 0; i < 2; i++) {
            int t = i * 256 + tid;
            int r = t >> 3, c0 = (t & 7) * 8;
            const float* sp = src + (size_t)(m0 + r) * stride + off + c0;
            float4 a = *(const float4*)sp, b = *(const float4*)(sp + 4);
            uint4 pk = { pack_f16x2(a.x, a.y), pack_f16x2(a.z, a.w),
                         pack_f16x2(b.x, b.y), pack_f16x2(b.z, b.w) };
            *(uint4*)(As + r * 72 + c0) = pk;
        }
#pragma unroll
        for (int i = 0; i < 4; i++) {
            int t = i * 256 + tid;
            int r = t >> 3, c0 = (t & 7) * 8;
            *(uint4*)(Bs + r * 72 + c0) =
                *(const uint4*)(wT + (size_t)(n0 + r) * 704 + kc * 64 + c0);
        }
        __syncthreads();
#pragma unroll
        for (int ks = 0; ks < 4; ks++) {
            uint32_t a[4];
            LDSM4(a, aBase + ks * 32);
#pragma unroll
            for (int ntp = 0; ntp < 4; ntp++) {
                uint32_t b[4];
                LDSM4(b, bBase + ntp * (16 * 72 * 2) + ks * 32);
                mma16816(acc[2 * ntp],     a, b + 0);
                mma16816(acc[2 * ntp + 1], a, b + 2);
            }
        }
        __syncthreads();
    }

    int gid = lane >> 2, tig = lane & 3;
    int row = m0 + mt + gid;
#pragma unroll
    for (int nt = 0; nt < 8; nt++) {
        int col = n0 + ng + nt * 8 + 2 * tig;
        float b0 = bias[col], b1 = bias[col + 1];
        *(uint32_t*)(g_h1 + (size_t)row * 512 + col) =
            pack_f16x2(lrelu(acc[nt][0] + b0), lrelu(acc[nt][1] + b1));
        *(uint32_t*)(g_h1 + (size_t)(row + 8) * 512 + col) =
            pack_f16x2(lrelu(acc[nt][2] + b0), lrelu(acc[nt][3] + b1));
    }
}

// ---------------- head2: 512 -> 256 via f16 mma, lrelu, h2 fp32 ---------------
__global__ __launch_bounds__(256, 3) void head2_mma(const __half* __restrict__ wT,
                                                    const float* __restrict__ bias) {
    __shared__ __align__(16) __half As[64 * 72];
    __shared__ __align__(16) __half Bs[128 * 72];
    int tid = threadIdx.x, w = tid >> 5, lane = tid & 31;
    int m0 = blockIdx.x * 64, n0 = blockIdx.y * 128;
    int mt = (w >> 1) * 16, ng = (w & 1) * 64;

    float acc[8][4];
#pragma unroll
    for (int nt = 0; nt < 8; nt++)
#pragma unroll
        for (int j = 0; j < 4; j++) acc[nt][j] = 0.f;

    uint32_t aBase = smem_u32(As) +
        (uint32_t)(((mt + (lane & 15)) * 72 + (lane >> 4) * 8) * 2);
    uint32_t bBase = smem_u32(Bs) +
        (uint32_t)(((ng + (lane & 7) + ((lane >> 4) << 3)) * 72 + ((lane >> 3) & 1) * 8) * 2);

#pragma unroll 1
    for (int kc = 0; kc < 8; kc++) {
#pragma unroll
        for (int i = 0; i < 2; i++) {
            int t = i * 256 + tid;
            int r = t >> 3, c0 = (t & 7) * 8;
            *(uint4*)(As + r * 72 + c0) =
                *(const uint4*)(g_h1 + (size_t)(m0 + r) * 512 + kc * 64 + c0);
        }
#pragma unroll
        for (int i = 0; i < 4; i++) {
            int t = i * 256 + tid;
            int r = t >> 3, c0 = (t & 7) * 8;
            *(uint4*)(Bs + r * 72 + c0) =
                *(const uint4*)(wT + (size_t)(n0 + r) * 512 + kc * 64 + c0);
        }
        __syncthreads();
#pragma unroll
        for (int ks = 0; ks < 4; ks++) {
            uint32_t a[4];
            LDSM4(a, aBase + ks * 32);
#pragma unroll
            for (int ntp = 0; ntp < 4; ntp++) {
                uint32_t b[4];
                LDSM4(b, bBase + ntp * (16 * 72 * 2) + ks * 32);
                mma16816(acc[2 * ntp],     a, b + 0);
                mma16816(acc[2 * ntp + 1], a, b + 2);
            }
        }
        __syncthreads();
    }

    int gid = lane >> 2, tig = lane & 3;
    int row = m0 + mt + gid;
#pragma unroll
    for (int nt = 0; nt < 8; nt++) {
        int col = n0 + ng + nt * 8 + 2 * tig;
        float b0 = bias[col], b1 = bias[col + 1];
        g_h2[(size_t)row * 256 + col]           = lrelu(acc[nt][0] + b0);
        g_h2[(size_t)row * 256 + col + 1]       = lrelu(acc[nt][1] + b1);
        g_h2[(size_t)(row + 8) * 256 + col]     = lrelu(acc[nt][2] + b0);
        g_h2[(size_t)(row + 8) * 256 + col + 1] = lrelu(acc[nt][3] + b1);
    }
}

// ---------------- head3: 256 -> 12 (fp32, no lrelu) ----------------
__global__ __launch_bounds__(192) void head3_kernel(const float* __restrict__ wf3,
                                                    const float* __restrict__ bf3,
                                                    float* __restrict__ out) {
    int blk = blockIdx.x, tid = threadIdx.x;
    int r = tid / 12, c = tid - r * 12;
    int row = blk * 16 + r;
    const float* h = g_h2 + (size_t)row * 256;
    float a0 = bf3[c], a1 = 0.f, a2 = 0.f, a3 = 0.f;
#pragma unroll 4
    for (int cm = 0; cm < 256; cm += 4) {
        a0 = fmaf(h[cm + 0], wf3[(cm + 0) * 12 + c], a0);
        a1 = fmaf(h[cm + 1], wf3[(cm + 1) * 12 + c], a1);
        a2 = fmaf(h[cm + 2], wf3[(cm + 2) * 12 + c], a2);
        a3 = fmaf(h[cm + 3], wf3[(cm + 3) * 12 + c], a3);
    }
    out[(size_t)row * 12 + c] = (a0 + a1) + (a2 + a3);
}

// ---------------- launch ----------------
constexpr int SMEM_P1 = (2 * 64 * 4 + 32 * 4 + 64) * 4;
constexpr int SMEM_P2 = (2 * 64 * 68 + 32 * 68 + 64) * 4;
constexpr int SMEM_P3 = (2 * 128 * 68 + 32 * 132 + 128) * 4;              // 87040
constexpr int SMEM_ES  = (128 * 72 + 64 * 72) * 2 + 128 * 4 + 8 * 64 * 4; // 30208
constexpr int SMEM_EB2 = (256 * 72 + 64 * 72) * 2 + 256 * 4;              // 47104
constexpr int SMEM_EB3 = (256 * 136 + 64 * 136) * 2 + 256 * 4;            // 88064

extern "C" void kernel_launch(void* const* d_in, const int* in_sizes, int n_in,
                              void* d_out, int out_size) {
    const float* x   = (const float*)d_in[0];
    const float* pos = (const float*)d_in[1];
    const float* w1a = (const float*)d_in[2];
    const float* b1a = (const float*)d_in[3];
    const float* w1b = (const float*)d_in[4];
    const float* b1b = (const float*)d_in[5];
    const float* w2a = (const float*)d_in[6];
    const float* b2a = (const float*)d_in[7];
    const float* w2b = (const float*)d_in[8];
    const float* b2b = (const float*)d_in[9];
    const float* w3a = (const float*)d_in[10];
    const float* b3a = (const float*)d_in[11];
    const float* w3b = (const float*)d_in[12];
    const float* b3b = (const float*)d_in[13];
    const float* wf1 = (const float*)d_in[14];
    const float* bf1 = (const float*)d_in[15];
    const float* wf2 = (const float*)d_in[16];
    const float* bf2 = (const float*)d_in[17];
    const float* wf3 = (const float*)d_in[18];
    const float* bf3 = (const float*)d_in[19];
    float* out = (float*)d_out;

    float *x1p, *x2p, *x3p;
    __half *wt1p, *wt2p, *wt3p, *wf1Tp, *wf2Tp;
    cudaGetSymbolAddress((void**)&x1p, g_x1);
    cudaGetSymbolAddress((void**)&x2p, g_x2);
    cudaGetSymbolAddress((void**)&x3p, g_x3);
    cudaGetSymbolAddress((void**)&wt1p, g_wbT1);
    cudaGetSymbolAddress((void**)&wt2p, g_wbT2);
    cudaGetSymbolAddress((void**)&wt3p, g_wbT3);
    cudaGetSymbolAddress((void**)&wf1Tp, g_wf1T);
    cudaGetSymbolAddress((void**)&wf2Tp, g_wf2T);

    static bool attr_done = false;
    if (!attr_done) {
        cudaFuncSetAttribute(proj3_kernel,
                             cudaFuncAttributeMaxDynamicSharedMemorySize, SMEM_P3);
        cudaFuncSetAttribute(edge_mma_s<64, 64, 1>,
                             cudaFuncAttributeMaxDynamicSharedMemorySize, SMEM_ES);
        cudaFuncSetAttribute(edge_mma_b<64, 128, 2>,
                             cudaFuncAttributeMaxDynamicSharedMemorySize, SMEM_EB2);
        cudaFuncSetAttribute(edge_mma_b<128, 512, 8>,
                             cudaFuncAttributeMaxDynamicSharedMemorySize, SMEM_EB3);
        attr_done = true;
    }

    prep_misc<<<368, 256>>>(pos, w1b, w2b, w3b, wt1p, wt2p, wt3p);         // 1
    knn_kernel<<<BN_, 256>>>();                                            // 2
    proj_kernel<3, 64, 4><<<BN_ / 32, 256, SMEM_P1>>>(x, w1a, b1a);        // 3
    edge_mma_s<64, 64, 1><<<BN_ / 4, 256, SMEM_ES>>>(wt1p, b1b, x1p);      // 4 <- ncu
    prep_wf<<<1920, 256>>>(wf1, wf2, wf1Tp, wf2Tp);                        // 5

    // block2: 64 -> 64 -> 128
    proj_kernel<64, 64, 68><<<BN_ / 32, 256, SMEM_P2>>>(x1p, w2a, b2a);
    edge_mma_b<64, 128, 2><<<BN_ / 8, 256, SMEM_EB2>>>(wt2p, b2b, x2p);
    // block3: 128 -> 128 -> 512
    proj3_kernel<<<BN_ / 32, 256, SMEM_P3>>>(x2p, w3a, b3a);
    edge_mma_b<128, 512, 8><<<BN_ / 8, 256, SMEM_EB3>>>(wt3p, b3b, x3p);

    // head: 704 -> 512 (f16 mma) -> 256 (f16 mma) -> 12 (fp32)
    head1_mma<<<dim3(BN_ / 64, 4), 256>>>(wf1Tp, bf1);
    head2_mma<<<dim3(BN_ / 64, 2), 256>>>(wf2Tp, bf2);
    head3_kernel<<<BN_ / 16, 192>>>(wf3, bf3, out);
}